// round 5
// baseline (speedup 1.0000x reference)
#include <cuda_runtime.h>

// SineRnn: persistent 2-layer LSTM, B=256, T=512, predict=32, H=512.
// 128 CTAs x 512 threads. Column-partitioned (4 units/CTA), weights in SMEM,
// h exchanged via device-global double buffers + grid barrier, FFMA2 compute.

#define Hn    512
#define Bn    256
#define Tn    512
#define Pn    32
#define TPn   544
#define NCTA  128
#define NTHR  512
#define K2n   256   // H/2 k-pairs
#define CHn   16    // k2 per staged chunk
#define NCHUNK 16
#define ZP    260   // zbuf padded stride

__device__ float2   g_h1[2][K2n * Bn];
__device__ float2   g_h2[2][K2n * Bn];
__device__ float    g_out[TPn * Bn];
__device__ unsigned g_cnt;
__device__ unsigned g_gen;

struct Smem {
  float2 wh1[K2n * 16];     // 32 KB  [k2][gc] gate-col pairs (k even, k odd)
  float2 wx2[K2n * 16];     // 32 KB
  float2 wh2[K2n * 16];     // 32 KB
  float2 hs[2][CHn * Bn];   // 64 KB  double-buffered h staging [k2l][b]
  float  zbuf[16 * ZP];     // padded z exchange
  float  c1[4 * Bn];
  float  c2[4 * Bn];
  float  wx1[16];
  float  bias1[16];
  float  bias2[16];
  float  wl[4];
  float  red[16];
};

__device__ __forceinline__ float2 ffma2(float2 a, float2 b, float2 c) {
  unsigned long long au = *reinterpret_cast<unsigned long long*>(&a);
  unsigned long long bu = *reinterpret_cast<unsigned long long*>(&b);
  unsigned long long cu = *reinterpret_cast<unsigned long long*>(&c);
  unsigned long long du;
  asm("fma.rn.f32x2 %0, %1, %2, %3;" : "=l"(du) : "l"(au), "l"(bu), "l"(cu));
  return *reinterpret_cast<float2*>(&du);
}

__device__ __forceinline__ void cp_async16(void* sdst, const void* gsrc) {
  unsigned sa = (unsigned)__cvta_generic_to_shared(sdst);
  asm volatile("cp.async.cg.shared.global [%0], [%1], 16;\n" :: "r"(sa), "l"(gsrc));
}
__device__ __forceinline__ void cp_commit() { asm volatile("cp.async.commit_group;\n"); }
__device__ __forceinline__ void cp_wait1()  { asm volatile("cp.async.wait_group 1;\n"); }
__device__ __forceinline__ void cp_wait0()  { asm volatile("cp.async.wait_group 0;\n"); }

__device__ __forceinline__ float sigf(float x) { return 1.f / (1.f + expf(-x)); }

__device__ __forceinline__ void grid_barrier() {
  __threadfence();
  __syncthreads();
  if (threadIdx.x == 0) {
    volatile unsigned* vgen = &g_gen;
    unsigned gen = *vgen;
    __threadfence();
    unsigned ticket = atomicAdd(&g_cnt, 1u);
    if (ticket == (unsigned)gridDim.x - 1u) {
      g_cnt = 0u;
      __threadfence();
      *vgen = gen + 1u;
    } else {
      while (*vgen == gen) { __nanosleep(64); }
    }
    __threadfence();
  }
  __syncthreads();
}

__device__ __forceinline__ void stage_chunk(float4* dst, const float4* src, int tid) {
#pragma unroll
  for (int i = 0; i < 4; ++i)
    cp_async16(dst + i * NTHR + tid, src + i * NTHR + tid);
  cp_commit();
}

// Accumulate one full h-matrix pass. DUAL: za += h@Wa and zb += h@Wb.
// Each thread: 4 batches (b0..b0+3) x 2 gate cols (2*gcp, 2*gcp+1).
template <bool DUAL>
__device__ __forceinline__ void mat_pass(
    Smem* s, const float2* __restrict__ gsrc,
    const float2* __restrict__ wsA, const float2* __restrict__ wsB,
    float2 (&za)[4][2], float2 (&zb)[4][2],
    int tid, int bg, int gcp)
{
  const float4* src4 = reinterpret_cast<const float4*>(gsrc);
  float4* hb0 = reinterpret_cast<float4*>(s->hs[0]);
  float4* hb1 = reinterpret_cast<float4*>(s->hs[1]);
  stage_chunk(hb0, src4, tid);
  for (int c = 0; c < NCHUNK; ++c) {
    float4* cur = (c & 1) ? hb1 : hb0;
    if (c + 1 < NCHUNK) {
      stage_chunk((c & 1) ? hb0 : hb1, src4 + (c + 1) * (CHn * Bn / 2), tid);
      cp_wait1();
    } else {
      cp_wait0();
    }
    __syncthreads();
    const float4* wA = reinterpret_cast<const float4*>(wsA) + (c * CHn) * 8 + gcp;
    const float4* wB = reinterpret_cast<const float4*>(wsB) + (c * CHn) * 8 + gcp;
    const float4* hp = cur + bg * 2;
#pragma unroll 8
    for (int k2l = 0; k2l < CHn; ++k2l) {
      float4 hv[2];
#pragma unroll
      for (int i = 0; i < 2; ++i) hv[i] = hp[k2l * (Bn / 2) + i];
      float4 A = wA[k2l * 8];
      float2 a0 = make_float2(A.x, A.y);
      float2 a1 = make_float2(A.z, A.w);
      float2 b0v, b1v;
      if (DUAL) {
        float4 Bv = wB[k2l * 8];
        b0v = make_float2(Bv.x, Bv.y);
        b1v = make_float2(Bv.z, Bv.w);
      }
#pragma unroll
      for (int i = 0; i < 2; ++i) {
        float2 hlo = make_float2(hv[i].x, hv[i].y);   // batch b0+2i
        float2 hhi = make_float2(hv[i].z, hv[i].w);   // batch b0+2i+1
        za[2 * i + 0][0] = ffma2(hlo, a0, za[2 * i + 0][0]);
        za[2 * i + 0][1] = ffma2(hlo, a1, za[2 * i + 0][1]);
        za[2 * i + 1][0] = ffma2(hhi, a0, za[2 * i + 1][0]);
        za[2 * i + 1][1] = ffma2(hhi, a1, za[2 * i + 1][1]);
        if (DUAL) {
          zb[2 * i + 0][0] = ffma2(hlo, b0v, zb[2 * i + 0][0]);
          zb[2 * i + 0][1] = ffma2(hlo, b1v, zb[2 * i + 0][1]);
          zb[2 * i + 1][0] = ffma2(hhi, b0v, zb[2 * i + 1][0]);
          zb[2 * i + 1][1] = ffma2(hhi, b1v, zb[2 * i + 1][1]);
        }
      }
    }
    __syncthreads();
  }
}

__global__ void __launch_bounds__(NTHR, 1) sine_rnn_kernel(
    const float* __restrict__ seq,
    const float* __restrict__ Wx1, const float* __restrict__ bx1,
    const float* __restrict__ Wh1, const float* __restrict__ bh1,
    const float* __restrict__ Wx2, const float* __restrict__ bx2,
    const float* __restrict__ Wh2, const float* __restrict__ bh2,
    const float* __restrict__ Wl,  const float* __restrict__ bl,
    float* __restrict__ out)
{
  extern __shared__ char smem_raw[];
  Smem* s = reinterpret_cast<Smem*>(smem_raw);

  const int tid  = threadIdx.x;
  const int lane = tid & 31;
  const int warp = tid >> 5;
  const int gcp  = lane & 7;                // gate-col pair (gc = 2*gcp, 2*gcp+1)
  const int bg   = warp * 4 + (lane >> 3);  // batch quad index 0..63
  const int b0   = bg * 4;
  const int cta  = blockIdx.x;
  const int u0   = cta * 4;
  const float bl0 = bl[0];

  // ---------------- one-time init ----------------
  {
    float* wh1f = reinterpret_cast<float*>(s->wh1);
    float* wx2f = reinterpret_cast<float*>(s->wx2);
    float* wh2f = reinterpret_cast<float*>(s->wh2);
    for (int idx = tid; idx < Hn * 16; idx += NTHR) {
      int k = idx >> 4, gc = idx & 15;
      int col = u0 + (gc & 3) + ((gc >> 2) << 9);
      int dst = ((k >> 1) * 16 + gc) * 2 + (k & 1);
      wh1f[dst] = Wh1[k * 2048 + col];
      wx2f[dst] = Wx2[k * 2048 + col];
      wh2f[dst] = Wh2[k * 2048 + col];
    }
    if (tid < 16) {
      int gc = tid;
      int col = u0 + (gc & 3) + ((gc >> 2) << 9);
      s->wx1[gc]   = Wx1[col];
      s->bias1[gc] = bx1[col] + bh1[col];
      s->bias2[gc] = bx2[col] + bh2[col];
    }
    if (tid < 4) s->wl[tid] = Wl[u0 + tid];
    for (int i = tid; i < 4 * Bn; i += NTHR) { s->c1[i] = 0.f; s->c2[i] = 0.f; }
  }
  __syncthreads();

  // h1(0) from x(0), c1(-1)=0 ; zero slice of g_h2[1] (h2(-1)=0)
  if (tid < Bn) {
    int b = tid;
    float x0 = seq[b * Tn + 0];
    float hv[4];
#pragma unroll
    for (int u = 0; u < 4; ++u) {
      float zi = fmaf(x0, s->wx1[u],      s->bias1[u]);
      float zo = fmaf(x0, s->wx1[8 + u],  s->bias1[8 + u]);
      float zg = fmaf(x0, s->wx1[12 + u], s->bias1[12 + u]);
      float ii = sigf(zi), oo = sigf(zo), gg = tanhf(zg);
      float c = ii * gg;
      s->c1[u * Bn + b] = c;
      hv[u] = oo * tanhf(c);
    }
    float2* dst = g_h1[0] + b;
    dst[(2 * cta + 0) * Bn] = make_float2(hv[0], hv[1]);
    dst[(2 * cta + 1) * Bn] = make_float2(hv[2], hv[3]);
  }
  for (int i = tid; i < 512; i += NTHR)
    g_h2[1][cta * 512 + i] = make_float2(0.f, 0.f);
  grid_barrier();

  // ---------------- recurrence ----------------
  for (int t = 0; t < TPn; ++t) {
    const bool pred = (t >= Tn - 1);

    // deterministic output o(t-1) for main-phase steps (owner CTA, 2 batches)
    if (t >= 1 && t <= Tn - 1) {
      int ob = 2 * cta + (tid >> 8);  // warps 0-7 -> batch 2*cta, 8-15 -> +1
      int kq = tid & 255;
      const float2* col = g_h2[(t - 1) & 1] + ob;
      float2 hA = __ldcg(&col[kq * Bn]);
      float2 w  = reinterpret_cast<const float2*>(Wl)[kq];
      float p = hA.x * w.x + hA.y * w.y;
#pragma unroll
      for (int off = 16; off; off >>= 1) p += __shfl_xor_sync(0xffffffffu, p, off);
      if (lane == 0) s->red[warp] = p;
      __syncthreads();
      if (tid < 2) {
        float* r = s->red + tid * 8;
        float acc = 0.f;
#pragma unroll
        for (int i = 0; i < 8; ++i) acc += r[i];
        g_out[(t - 1) * Bn + 2 * cta + tid] = acc;
      }
      __syncthreads();
    }

    float2 z1a[4][2], z2a[4][2];
#pragma unroll
    for (int i = 0; i < 4; ++i)
#pragma unroll
      for (int j = 0; j < 2; ++j) {
        z1a[i][j] = make_float2(0.f, 0.f);
        z2a[i][j] = make_float2(0.f, 0.f);
      }

    // z2 += h2(t-1) @ Wh2
    mat_pass<false>(s, g_h2[(t ^ 1) & 1], s->wh2, s->wh2, z2a, z1a, tid, bg, gcp);
    // z2 += h1(t) @ Wx2 ; z1 += h1(t) @ Wh1   (single staging pass)
    mat_pass<true>(s, g_h1[t & 1], s->wx2, s->wh1, z2a, z1a, tid, bg, gcp);

    // ---- combine layer 2 -> h2(t), publish ----
#pragma unroll
    for (int bb = 0; bb < 4; ++bb)
#pragma unroll
      for (int j = 0; j < 2; ++j) {
        int gc = 2 * gcp + j;
        s->zbuf[gc * ZP + b0 + bb] = z2a[bb][j].x + z2a[bb][j].y + s->bias2[gc];
      }
    __syncthreads();
    if (tid < Bn) {
      int b = tid;
      float hv[4];
#pragma unroll
      for (int u = 0; u < 4; ++u) {
        float zi = s->zbuf[(u) * ZP + b];
        float zf = s->zbuf[(4 + u) * ZP + b];
        float zo = s->zbuf[(8 + u) * ZP + b];
        float zg = s->zbuf[(12 + u) * ZP + b];
        float ii = sigf(zi), ff = sigf(zf), oo = sigf(zo), gg = tanhf(zg);
        float c = ff * s->c2[u * Bn + b] + ii * gg;
        s->c2[u * Bn + b] = c;
        hv[u] = oo * tanhf(c);
      }
      float2* dst = g_h2[t & 1] + b;
      dst[(2 * cta + 0) * Bn] = make_float2(hv[0], hv[1]);
      dst[(2 * cta + 1) * Bn] = make_float2(hv[2], hv[3]);
    }
    __syncthreads();

    // ---- next-step input x(t+1) ----
    float xnext = 0.f;
    if (!pred) {
      if (tid < Bn) xnext = seq[tid * Tn + (t + 1)];
    } else {
      grid_barrier();  // h2(t) visible everywhere
      if (tid < Bn) {
        const float2* h2col = g_h2[t & 1] + tid;
        const float2* wl2 = reinterpret_cast<const float2*>(Wl);
        float o = 0.f;
        for (int k2 = 0; k2 < K2n; ++k2) {
          float2 hv = __ldcg(&h2col[k2 * Bn]);
          float2 wv = wl2[k2];
          o = fmaf(hv.x, wv.x, o);
          o = fmaf(hv.y, wv.y, o);
        }
        if (cta == 0) g_out[t * Bn + tid] = o;
        xnext = o + bl0;
      }
    }

    // ---- combine layer 1 -> h1(t+1), publish ----
#pragma unroll
    for (int bb = 0; bb < 4; ++bb)
#pragma unroll
      for (int j = 0; j < 2; ++j) {
        int gc = 2 * gcp + j;
        s->zbuf[gc * ZP + b0 + bb] = z1a[bb][j].x + z1a[bb][j].y + s->bias1[gc];
      }
    __syncthreads();
    if (tid < Bn) {
      int b = tid;
      float x = xnext;
      float hv[4];
#pragma unroll
      for (int u = 0; u < 4; ++u) {
        float zi = fmaf(x, s->wx1[u],      s->zbuf[(u) * ZP + b]);
        float zf = fmaf(x, s->wx1[4 + u],  s->zbuf[(4 + u) * ZP + b]);
        float zo = fmaf(x, s->wx1[8 + u],  s->zbuf[(8 + u) * ZP + b]);
        float zg = fmaf(x, s->wx1[12 + u], s->zbuf[(12 + u) * ZP + b]);
        float ii = sigf(zi), ff = sigf(zf), oo = sigf(zo), gg = tanhf(zg);
        float c = ff * s->c1[u * Bn + b] + ii * gg;
        s->c1[u * Bn + b] = c;
        hv[u] = oo * tanhf(c);
      }
      float2* dst = g_h1[(t + 1) & 1] + b;
      dst[(2 * cta + 0) * Bn] = make_float2(hv[0], hv[1]);
      dst[(2 * cta + 1) * Bn] = make_float2(hv[2], hv[3]);
    }
    grid_barrier();
  }

  // ---------------- output copy: out[b][tp] = o + bl ----------------
  for (int idx = cta * NTHR + tid; idx < TPn * Bn; idx += NCTA * NTHR) {
    int b = idx / TPn, tp = idx - b * TPn;
    out[idx] = __ldcg(&g_out[tp * Bn + b]) + bl0;
  }
}

extern "C" void kernel_launch(void* const* d_in, const int* in_sizes, int n_in,
                              void* d_out, int out_size) {
  (void)in_sizes; (void)n_in; (void)out_size;
  const float* seq = (const float*)d_in[0];
  // d_in[1] = predict (int scalar, fixed at 32)
  const float* Wx1 = (const float*)d_in[2];
  const float* bx1 = (const float*)d_in[3];
  const float* Wh1 = (const float*)d_in[4];
  const float* bh1 = (const float*)d_in[5];
  const float* Wx2 = (const float*)d_in[6];
  const float* bx2 = (const float*)d_in[7];
  const float* Wh2 = (const float*)d_in[8];
  const float* bh2 = (const float*)d_in[9];
  const float* Wl  = (const float*)d_in[10];
  const float* bl  = (const float*)d_in[11];

  cudaFuncSetAttribute(sine_rnn_kernel,
                       cudaFuncAttributeMaxDynamicSharedMemorySize,
                       (int)sizeof(Smem));
  sine_rnn_kernel<<<NCTA, NTHR, sizeof(Smem)>>>(
      seq, Wx1, bx1, Wh1, bh1, Wx2, bx2, Wh2, bh2, Wl, bl, (float*)d_out);
}

// round 6
// speedup vs baseline: 1.0012x; 1.0012x over previous
#include <cuda_runtime.h>

// SineRnn: persistent 2-layer LSTM, B=256, T=512, predict=32, H=512.
// 128 CTAs x 512 threads. Column-partitioned (4 units/CTA), weights in SMEM,
// h exchanged via device-global double buffers + grid barrier, FFMA2 compute.

#define Hn    512
#define Bn    256
#define Tn    512
#define Pn    32
#define TPn   544
#define NCTA  128
#define NTHR  512
#define K2n   256   // H/2 k-pairs
#define CHn   16    // k2 per staged chunk
#define NCHUNK 16
#define ZP    260   // zbuf padded stride

__device__ float2   g_h1[2][K2n * Bn];
__device__ float2   g_h2[2][K2n * Bn];
__device__ float    g_out[TPn * Bn];
__device__ unsigned g_cnt;
__device__ unsigned g_gen;

struct Smem {
  float2 wh1[K2n * 16];     // 32 KB  [k2][gc] gate-col pairs (k even, k odd)
  float2 wx2[K2n * 16];     // 32 KB
  float2 wh2[K2n * 16];     // 32 KB
  float2 hs[2][CHn * Bn];   // 64 KB  double-buffered h staging [k2l][b]
  float  zbuf[16 * ZP];     // padded z exchange
  float  c1[4 * Bn];
  float  c2[4 * Bn];
  float  wx1[16];
  float  bias1[16];
  float  bias2[16];
  float  wl[4];
  float  red[16];
};

__device__ __forceinline__ float2 ffma2(float2 a, float2 b, float2 c) {
  unsigned long long au = *reinterpret_cast<unsigned long long*>(&a);
  unsigned long long bu = *reinterpret_cast<unsigned long long*>(&b);
  unsigned long long cu = *reinterpret_cast<unsigned long long*>(&c);
  unsigned long long du;
  asm("fma.rn.f32x2 %0, %1, %2, %3;" : "=l"(du) : "l"(au), "l"(bu), "l"(cu));
  return *reinterpret_cast<float2*>(&du);
}

__device__ __forceinline__ void cp_async16(void* sdst, const void* gsrc) {
  unsigned sa = (unsigned)__cvta_generic_to_shared(sdst);
  asm volatile("cp.async.cg.shared.global [%0], [%1], 16;\n" :: "r"(sa), "l"(gsrc));
}
__device__ __forceinline__ void cp_commit() { asm volatile("cp.async.commit_group;\n"); }
__device__ __forceinline__ void cp_wait1()  { asm volatile("cp.async.wait_group 1;\n"); }
__device__ __forceinline__ void cp_wait0()  { asm volatile("cp.async.wait_group 0;\n"); }

__device__ __forceinline__ float sigf(float x) { return 1.f / (1.f + expf(-x)); }

__device__ __forceinline__ void grid_barrier() {
  __threadfence();
  __syncthreads();
  if (threadIdx.x == 0) {
    volatile unsigned* vgen = &g_gen;
    unsigned gen = *vgen;
    __threadfence();
    unsigned ticket = atomicAdd(&g_cnt, 1u);
    if (ticket == (unsigned)gridDim.x - 1u) {
      g_cnt = 0u;
      __threadfence();
      *vgen = gen + 1u;
    } else {
      while (*vgen == gen) { __nanosleep(64); }
    }
    __threadfence();
  }
  __syncthreads();
}

__device__ __forceinline__ void stage_chunk(float4* dst, const float4* src, int tid) {
#pragma unroll
  for (int i = 0; i < 4; ++i)
    cp_async16(dst + i * NTHR + tid, src + i * NTHR + tid);
  cp_commit();
}

// Accumulate one full h-matrix pass. DUAL: za += h@Wa and zb += h@Wb.
// Each thread: 4 batches (b0..b0+3) x 2 gate cols (2*gcp, 2*gcp+1).
template <bool DUAL>
__device__ __forceinline__ void mat_pass(
    Smem* s, const float2* __restrict__ gsrc,
    const float2* __restrict__ wsA, const float2* __restrict__ wsB,
    float2 (&za)[4][2], float2 (&zb)[4][2],
    int tid, int bg, int gcp)
{
  const float4* src4 = reinterpret_cast<const float4*>(gsrc);
  float4* hb0 = reinterpret_cast<float4*>(s->hs[0]);
  float4* hb1 = reinterpret_cast<float4*>(s->hs[1]);
  stage_chunk(hb0, src4, tid);
  for (int c = 0; c < NCHUNK; ++c) {
    float4* cur = (c & 1) ? hb1 : hb0;
    if (c + 1 < NCHUNK) {
      stage_chunk((c & 1) ? hb0 : hb1, src4 + (c + 1) * (CHn * Bn / 2), tid);
      cp_wait1();
    } else {
      cp_wait0();
    }
    __syncthreads();
    const float4* wA = reinterpret_cast<const float4*>(wsA) + (c * CHn) * 8 + gcp;
    const float4* wB = reinterpret_cast<const float4*>(wsB) + (c * CHn) * 8 + gcp;
    const float4* hp = cur + bg * 2;
#pragma unroll 8
    for (int k2l = 0; k2l < CHn; ++k2l) {
      float4 hv[2];
#pragma unroll
      for (int i = 0; i < 2; ++i) hv[i] = hp[k2l * (Bn / 2) + i];
      float4 A = wA[k2l * 8];
      float2 a0 = make_float2(A.x, A.y);
      float2 a1 = make_float2(A.z, A.w);
      float2 b0v, b1v;
      if (DUAL) {
        float4 Bv = wB[k2l * 8];
        b0v = make_float2(Bv.x, Bv.y);
        b1v = make_float2(Bv.z, Bv.w);
      }
#pragma unroll
      for (int i = 0; i < 2; ++i) {
        float2 hlo = make_float2(hv[i].x, hv[i].y);   // batch b0+2i
        float2 hhi = make_float2(hv[i].z, hv[i].w);   // batch b0+2i+1
        za[2 * i + 0][0] = ffma2(hlo, a0, za[2 * i + 0][0]);
        za[2 * i + 0][1] = ffma2(hlo, a1, za[2 * i + 0][1]);
        za[2 * i + 1][0] = ffma2(hhi, a0, za[2 * i + 1][0]);
        za[2 * i + 1][1] = ffma2(hhi, a1, za[2 * i + 1][1]);
        if (DUAL) {
          zb[2 * i + 0][0] = ffma2(hlo, b0v, zb[2 * i + 0][0]);
          zb[2 * i + 0][1] = ffma2(hlo, b1v, zb[2 * i + 0][1]);
          zb[2 * i + 1][0] = ffma2(hhi, b0v, zb[2 * i + 1][0]);
          zb[2 * i + 1][1] = ffma2(hhi, b1v, zb[2 * i + 1][1]);
        }
      }
    }
    __syncthreads();
  }
}

__global__ void __launch_bounds__(NTHR, 1) sine_rnn_kernel(
    const float* __restrict__ seq,
    const float* __restrict__ Wx1, const float* __restrict__ bx1,
    const float* __restrict__ Wh1, const float* __restrict__ bh1,
    const float* __restrict__ Wx2, const float* __restrict__ bx2,
    const float* __restrict__ Wh2, const float* __restrict__ bh2,
    const float* __restrict__ Wl,  const float* __restrict__ bl,
    float* __restrict__ out)
{
  extern __shared__ char smem_raw[];
  Smem* s = reinterpret_cast<Smem*>(smem_raw);

  const int tid  = threadIdx.x;
  const int lane = tid & 31;
  const int warp = tid >> 5;
  const int gcp  = lane & 7;                // gate-col pair (gc = 2*gcp, 2*gcp+1)
  const int bg   = warp * 4 + (lane >> 3);  // batch quad index 0..63
  const int b0   = bg * 4;
  const int cta  = blockIdx.x;
  const int u0   = cta * 4;
  const float bl0 = bl[0];

  // ---------------- one-time init ----------------
  {
    float* wh1f = reinterpret_cast<float*>(s->wh1);
    float* wx2f = reinterpret_cast<float*>(s->wx2);
    float* wh2f = reinterpret_cast<float*>(s->wh2);
    for (int idx = tid; idx < Hn * 16; idx += NTHR) {
      int k = idx >> 4, gc = idx & 15;
      int col = u0 + (gc & 3) + ((gc >> 2) << 9);
      int dst = ((k >> 1) * 16 + gc) * 2 + (k & 1);
      wh1f[dst] = Wh1[k * 2048 + col];
      wx2f[dst] = Wx2[k * 2048 + col];
      wh2f[dst] = Wh2[k * 2048 + col];
    }
    if (tid < 16) {
      int gc = tid;
      int col = u0 + (gc & 3) + ((gc >> 2) << 9);
      s->wx1[gc]   = Wx1[col];
      s->bias1[gc] = bx1[col] + bh1[col];
      s->bias2[gc] = bx2[col] + bh2[col];
    }
    if (tid < 4) s->wl[tid] = Wl[u0 + tid];
    for (int i = tid; i < 4 * Bn; i += NTHR) { s->c1[i] = 0.f; s->c2[i] = 0.f; }
  }
  __syncthreads();

  // h1(0) from x(0), c1(-1)=0 ; zero slice of g_h2[1] (h2(-1)=0)
  if (tid < Bn) {
    int b = tid;
    float x0 = seq[b * Tn + 0];
    float hv[4];
#pragma unroll
    for (int u = 0; u < 4; ++u) {
      float zi = fmaf(x0, s->wx1[u],      s->bias1[u]);
      float zo = fmaf(x0, s->wx1[8 + u],  s->bias1[8 + u]);
      float zg = fmaf(x0, s->wx1[12 + u], s->bias1[12 + u]);
      float ii = sigf(zi), oo = sigf(zo), gg = tanhf(zg);
      float c = ii * gg;
      s->c1[u * Bn + b] = c;
      hv[u] = oo * tanhf(c);
    }
    float2* dst = g_h1[0] + b;
    dst[(2 * cta + 0) * Bn] = make_float2(hv[0], hv[1]);
    dst[(2 * cta + 1) * Bn] = make_float2(hv[2], hv[3]);
  }
  for (int i = tid; i < 512; i += NTHR)
    g_h2[1][cta * 512 + i] = make_float2(0.f, 0.f);
  grid_barrier();

  // ---------------- recurrence ----------------
  for (int t = 0; t < TPn; ++t) {
    const bool pred = (t >= Tn - 1);

    // deterministic output o(t-1) for main-phase steps (owner CTA, 2 batches)
    if (t >= 1 && t <= Tn - 1) {
      int ob = 2 * cta + (tid >> 8);  // warps 0-7 -> batch 2*cta, 8-15 -> +1
      int kq = tid & 255;
      const float2* col = g_h2[(t - 1) & 1] + ob;
      float2 hA = __ldcg(&col[kq * Bn]);
      float2 w  = reinterpret_cast<const float2*>(Wl)[kq];
      float p = hA.x * w.x + hA.y * w.y;
#pragma unroll
      for (int off = 16; off; off >>= 1) p += __shfl_xor_sync(0xffffffffu, p, off);
      if (lane == 0) s->red[warp] = p;
      __syncthreads();
      if (tid < 2) {
        float* r = s->red + tid * 8;
        float acc = 0.f;
#pragma unroll
        for (int i = 0; i < 8; ++i) acc += r[i];
        g_out[(t - 1) * Bn + 2 * cta + tid] = acc;
      }
      __syncthreads();
    }

    float2 z1a[4][2], z2a[4][2];
#pragma unroll
    for (int i = 0; i < 4; ++i)
#pragma unroll
      for (int j = 0; j < 2; ++j) {
        z1a[i][j] = make_float2(0.f, 0.f);
        z2a[i][j] = make_float2(0.f, 0.f);
      }

    // z2 += h2(t-1) @ Wh2
    mat_pass<false>(s, g_h2[(t ^ 1) & 1], s->wh2, s->wh2, z2a, z1a, tid, bg, gcp);
    // z2 += h1(t) @ Wx2 ; z1 += h1(t) @ Wh1   (single staging pass)
    mat_pass<true>(s, g_h1[t & 1], s->wx2, s->wh1, z2a, z1a, tid, bg, gcp);

    // ---- combine layer 2 -> h2(t), publish ----
#pragma unroll
    for (int bb = 0; bb < 4; ++bb)
#pragma unroll
      for (int j = 0; j < 2; ++j) {
        int gc = 2 * gcp + j;
        s->zbuf[gc * ZP + b0 + bb] = z2a[bb][j].x + z2a[bb][j].y + s->bias2[gc];
      }
    __syncthreads();
    if (tid < Bn) {
      int b = tid;
      float hv[4];
#pragma unroll
      for (int u = 0; u < 4; ++u) {
        float zi = s->zbuf[(u) * ZP + b];
        float zf = s->zbuf[(4 + u) * ZP + b];
        float zo = s->zbuf[(8 + u) * ZP + b];
        float zg = s->zbuf[(12 + u) * ZP + b];
        float ii = sigf(zi), ff = sigf(zf), oo = sigf(zo), gg = tanhf(zg);
        float c = ff * s->c2[u * Bn + b] + ii * gg;
        s->c2[u * Bn + b] = c;
        hv[u] = oo * tanhf(c);
      }
      float2* dst = g_h2[t & 1] + b;
      dst[(2 * cta + 0) * Bn] = make_float2(hv[0], hv[1]);
      dst[(2 * cta + 1) * Bn] = make_float2(hv[2], hv[3]);
    }
    __syncthreads();

    // ---- next-step input x(t+1) ----
    float xnext = 0.f;
    if (!pred) {
      if (tid < Bn) xnext = seq[tid * Tn + (t + 1)];
    } else {
      grid_barrier();  // h2(t) visible everywhere
      if (tid < Bn) {
        const float2* h2col = g_h2[t & 1] + tid;
        const float2* wl2 = reinterpret_cast<const float2*>(Wl);
        float o = 0.f;
        for (int k2 = 0; k2 < K2n; ++k2) {
          float2 hv = __ldcg(&h2col[k2 * Bn]);
          float2 wv = wl2[k2];
          o = fmaf(hv.x, wv.x, o);
          o = fmaf(hv.y, wv.y, o);
        }
        if (cta == 0) g_out[t * Bn + tid] = o;
        xnext = o + bl0;
      }
    }

    // ---- combine layer 1 -> h1(t+1), publish ----
#pragma unroll
    for (int bb = 0; bb < 4; ++bb)
#pragma unroll
      for (int j = 0; j < 2; ++j) {
        int gc = 2 * gcp + j;
        s->zbuf[gc * ZP + b0 + bb] = z1a[bb][j].x + z1a[bb][j].y + s->bias1[gc];
      }
    __syncthreads();
    if (tid < Bn) {
      int b = tid;
      float x = xnext;
      float hv[4];
#pragma unroll
      for (int u = 0; u < 4; ++u) {
        float zi = fmaf(x, s->wx1[u],      s->zbuf[(u) * ZP + b]);
        float zf = fmaf(x, s->wx1[4 + u],  s->zbuf[(4 + u) * ZP + b]);
        float zo = fmaf(x, s->wx1[8 + u],  s->zbuf[(8 + u) * ZP + b]);
        float zg = fmaf(x, s->wx1[12 + u], s->zbuf[(12 + u) * ZP + b]);
        float ii = sigf(zi), ff = sigf(zf), oo = sigf(zo), gg = tanhf(zg);
        float c = ff * s->c1[u * Bn + b] + ii * gg;
        s->c1[u * Bn + b] = c;
        hv[u] = oo * tanhf(c);
      }
      float2* dst = g_h1[(t + 1) & 1] + b;
      dst[(2 * cta + 0) * Bn] = make_float2(hv[0], hv[1]);
      dst[(2 * cta + 1) * Bn] = make_float2(hv[2], hv[3]);
    }
    grid_barrier();
  }

  // ---------------- output copy: out[b][tp] = o + bl ----------------
  for (int idx = cta * NTHR + tid; idx < TPn * Bn; idx += NCTA * NTHR) {
    int b = idx / TPn, tp = idx - b * TPn;
    out[idx] = __ldcg(&g_out[tp * Bn + b]) + bl0;
  }
}

extern "C" void kernel_launch(void* const* d_in, const int* in_sizes, int n_in,
                              void* d_out, int out_size) {
  (void)in_sizes; (void)n_in; (void)out_size;
  const float* seq = (const float*)d_in[0];
  // d_in[1] = predict (int scalar, fixed at 32)
  const float* Wx1 = (const float*)d_in[2];
  const float* bx1 = (const float*)d_in[3];
  const float* Wh1 = (const float*)d_in[4];
  const float* bh1 = (const float*)d_in[5];
  const float* Wx2 = (const float*)d_in[6];
  const float* bx2 = (const float*)d_in[7];
  const float* Wh2 = (const float*)d_in[8];
  const float* bh2 = (const float*)d_in[9];
  const float* Wl  = (const float*)d_in[10];
  const float* bl  = (const float*)d_in[11];

  cudaFuncSetAttribute(sine_rnn_kernel,
                       cudaFuncAttributeMaxDynamicSharedMemorySize,
                       (int)sizeof(Smem));
  sine_rnn_kernel<<<NCTA, NTHR, sizeof(Smem)>>>(
      seq, Wx1, bx1, Wh1, bh1, Wx2, bx2, Wh2, bh2, Wl, bl, (float*)d_out);
}

// round 8
// speedup vs baseline: 1.1798x; 1.1783x over previous
#include <cuda_runtime.h>
#include <cuda_fp16.h>

#define NCTA 128
#define NTHR 512
#define Tn   512
#define TPn  544

// SMEM byte map
#define SM_B      0          // 96KB weight fragments (hi/lo planes)
#define SM_CHUNK  98304      // 2 x 32KB A-chunk double buffer (+reduce slots)
#define SM_Z      163840     // 32*257 floats zbuf (also reduce slot3)
#define SM_MISC   196736     // bias1[16],bias2[16],wx1[16],wl[4]
#define SM_TOTAL  196992

#define BOFFU(m,q,p,nt,L) ((((((m)*32+(q))*2+(p))*2+(nt))*32+(L))*2)

__device__ __align__(16) unsigned g_h1[2][131072];  // fp16 planes, A-frag order
__device__ __align__(16) unsigned g_h2[2][131072];
__device__ float    g_opart[256 * NCTA];            // [b][cta]
__device__ float    g_out[TPn * 256];               // [t][b], raw (no bl)
__device__ unsigned g_flags[NCTA];

__device__ __forceinline__ float sigf(float x) { return 1.f / (1.f + __expf(-x)); }

__device__ __forceinline__ void mma16816(float* c, const unsigned* a, const unsigned* b) {
  asm volatile(
      "mma.sync.aligned.m16n8k16.row.col.f32.f16.f16.f32 "
      "{%0,%1,%2,%3},{%4,%5,%6,%7},{%8,%9},{%0,%1,%2,%3};\n"
      : "+f"(c[0]), "+f"(c[1]), "+f"(c[2]), "+f"(c[3])
      : "r"(a[0]), "r"(a[1]), "r"(a[2]), "r"(a[3]), "r"(b[0]), "r"(b[1]));
}

__device__ __forceinline__ void cp_async16(unsigned sdst, const void* gsrc) {
  asm volatile("cp.async.cg.shared.global [%0], [%1], 16;\n" :: "r"(sdst), "l"(gsrc));
}
__device__ __forceinline__ void cp_commit() { asm volatile("cp.async.commit_group;\n"); }
__device__ __forceinline__ void cp_wait1()  { asm volatile("cp.async.wait_group 1;\n"); }
__device__ __forceinline__ void cp_wait0()  { asm volatile("cp.async.wait_group 0;\n"); }

__device__ __forceinline__ void grid_barrier(unsigned& gen) {
  __threadfence();
  __syncthreads();
  ++gen;
  if (threadIdx.x == 0)
    asm volatile("st.release.gpu.u32 [%0], %1;" :: "l"(&g_flags[blockIdx.x]), "r"(gen));
  if (threadIdx.x < NCTA) {
    unsigned v;
    do {
      asm volatile("ld.acquire.gpu.u32 %0, [%1];" : "=r"(v) : "l"(&g_flags[threadIdx.x]));
    } while ((int)(v - gen) < 0);
  }
  __syncthreads();
}

// write h[b][u0..u0+3] as hi/lo fp16 planes in A-fragment order
__device__ __forceinline__ void h_write(unsigned* gb, int b, int cta, const float* hv) {
  int q = cta >> 2, kcb = (cta & 3) * 4, mtg = b >> 4;
  __half hh[4], hl[4];
#pragma unroll
  for (int u = 0; u < 4; ++u) {
    hh[u] = __float2half_rn(hv[u]);
    hl[u] = __float2half_rn(hv[u] - __half2float(hh[u]));
  }
#pragma unroll
  for (int j = 0; j < 2; ++j) {
    int kc0 = kcb + 2 * j;
    int L   = ((b & 7) << 2) | ((kc0 & 7) >> 1);
    int rg  = ((b >> 3) & 1) | ((kc0 >> 3) << 1);
    __half2 vh = __halves2half2(hh[2 * j], hh[2 * j + 1]);
    __half2 vl = __halves2half2(hl[2 * j], hl[2 * j + 1]);
    gb[((q * 2 + 0) * 16 + mtg) * 128 + L * 4 + rg] = *reinterpret_cast<unsigned*>(&vh);
    gb[((q * 2 + 1) * 16 + mtg) * 128 + L * 4 + rg] = *reinterpret_cast<unsigned*>(&vl);
  }
}

// stage one round: q = kpi*8+rr for kpi 0..3, given plane p, into chunk buf
__device__ __forceinline__ void stage(unsigned sb, int buf, const unsigned* gbase,
                                      int p, int rr, int tid) {
  int kpi = tid >> 7, i = tid & 127;
  int q = kpi * 8 + rr;
  const unsigned* src = gbase + (q * 2 + p) * 2048;
  unsigned dst = sb + SM_CHUNK + (unsigned)buf * 32768u + (unsigned)kpi * 8192u;
#pragma unroll
  for (int j = 0; j < 4; ++j) {
    int u = i + j * 128;
    cp_async16(dst + u * 16, src + u * 4);
  }
}

__global__ void __launch_bounds__(NTHR, 1) sine_rnn_kernel(
    const float* __restrict__ seq,
    const float* __restrict__ Wx1, const float* __restrict__ bx1,
    const float* __restrict__ Wh1, const float* __restrict__ bh1,
    const float* __restrict__ Wx2, const float* __restrict__ bx2,
    const float* __restrict__ Wh2, const float* __restrict__ bh2,
    const float* __restrict__ Wl,  const float* __restrict__ bl,
    float* __restrict__ out)
{
  extern __shared__ char smem[];
  const unsigned sb = (unsigned)__cvta_generic_to_shared(smem);
  const int tid  = threadIdx.x;
  const int lane = tid & 31;
  const int warp = tid >> 5;
  const int kp   = warp & 3;   // K-part (128 k each)
  const int mp   = warp >> 2;  // M-part (64 batches each)
  const int cta  = blockIdx.x;
  const int u0   = cta * 4;
  const float bl0 = __ldg(&bl[0]);

  float* misc = reinterpret_cast<float*>(smem + SM_MISC);
  // ---- init: weight fragments (hi/lo) + misc ----
  for (int idx = tid; idx < 3 * 512 * 16; idx += NTHR) {
    int m = idx >> 13, r = idx & 8191, k = r >> 4, gc = r & 15;
    int col = u0 + (gc & 3) + ((gc >> 2) << 9);
    const float* Wm = (m == 0) ? Wh2 : ((m == 1) ? Wx2 : Wh1);
    float v = Wm[k * 2048 + col];
    __half hi = __float2half_rn(v);
    __half lo = __float2half_rn(v - __half2float(hi));
    int q = k >> 4, kc = k & 15, nt = gc >> 3, n = gc & 7;
    int L = (n << 2) | ((kc & 7) >> 1), rg = kc >> 3, hf = kc & 1;
    __half* hp = reinterpret_cast<__half*>(smem + SM_B);
    hp[(BOFFU(m, q, 0, nt, L) + rg) * 2 + hf] = hi;
    hp[(BOFFU(m, q, 1, nt, L) + rg) * 2 + hf] = lo;
  }
  if (tid < 16) {
    int gc = tid;
    int col = u0 + (gc & 3) + ((gc >> 2) << 9);
    misc[gc]      = bx1[col] + bh1[col];
    misc[16 + gc] = bx2[col] + bh2[col];
    misc[32 + gc] = Wx1[col];
  }
  if (tid < 4) misc[48 + tid] = Wl[u0 + tid];
  __syncthreads();

  float c1s[4] = {0, 0, 0, 0}, c2s[4] = {0, 0, 0, 0};

  // h1(0) from x(0); zero slice of g_h2[1]
  if (tid < 256) {
    int b = tid;
    float x0 = __ldg(&seq[b * Tn]);
    float hv[4];
#pragma unroll
    for (int u = 0; u < 4; ++u) {
      float zi = fmaf(x0, misc[32 + u],      misc[u]);
      float zo = fmaf(x0, misc[32 + 8 + u],  misc[8 + u]);
      float zg = fmaf(x0, misc[32 + 12 + u], misc[12 + u]);
      float c = sigf(zi) * tanhf(zg);
      c1s[u] = c;
      hv[u] = sigf(zo) * tanhf(c);
    }
    h_write(g_h1[0], b, cta, hv);
  }
  for (int i = tid; i < 1024; i += NTHR) g_h2[1][cta * 1024 + i] = 0u;

  unsigned gen;
  asm volatile("ld.acquire.gpu.u32 %0, [%1];" : "=r"(gen) : "l"(&g_flags[cta]));
  grid_barrier(gen);

  for (int t = 0; t < TPn; ++t) {
    const bool pred = (t >= Tn - 1);

    // stage round 0 of phase 0
    stage(sb, 0, g_h2[(t ^ 1) & 1], 0, 0, tid);
    cp_commit();

    // main-phase o(t-1): owner reduces partials
    if (t >= 1 && t <= Tn - 1 && warp < 2) {
      int ob = 2 * cta + warp;
      float4 v = __ldcg(reinterpret_cast<const float4*>(g_opart + ob * NCTA) + lane);
      float p = v.x + v.y + v.z + v.w;
#pragma unroll
      for (int off = 16; off; off >>= 1) p += __shfl_xor_sync(0xffffffffu, p, off);
      if (lane == 0) g_out[(t - 1) * 256 + ob] = p;
    }

    float z2a[4][2][4], z1a[4][2][4];
#pragma unroll
    for (int i = 0; i < 32; ++i) {
      reinterpret_cast<float*>(z2a)[i] = 0.f;
      reinterpret_cast<float*>(z1a)[i] = 0.f;
    }

    // 32 chunks: phase = cc>>3 (h2hi, h2lo, h1hi, h1lo), rr = cc&7
    for (int cc = 0; cc < 32; ++cc) {
      if (cc < 31) {
        int nc = cc + 1, ph = nc >> 3;
        const unsigned* gsrc = (ph < 2) ? g_h2[(t ^ 1) & 1] : g_h1[t & 1];
        stage(sb, nc & 1, gsrc, ph & 1, nc & 7, tid);
        cp_commit();
        cp_wait1();
      } else {
        cp_wait0();
      }
      __syncthreads();
      {
        int phase = cc >> 3, rr = cc & 7;
        int q = kp * 8 + rr;
        const char* ab = smem + SM_CHUNK + (cc & 1) * 32768 +
                         ((kp * 16 + mp * 4) * 32 + lane) * 16;
        uint4 a[4];
#pragma unroll
        for (int mt = 0; mt < 4; ++mt)
          a[mt] = *reinterpret_cast<const uint4*>(ab + mt * 512);
        auto dob = [&](int m, int p, float (*acc)[2][4]) {
#pragma unroll
          for (int nt = 0; nt < 2; ++nt) {
            uint2 bv = *reinterpret_cast<const uint2*>(
                smem + SM_B + BOFFU(m, q, p, nt, lane) * 4);
#pragma unroll
            for (int mt = 0; mt < 4; ++mt)
              mma16816(acc[mt][nt], reinterpret_cast<const unsigned*>(&a[mt]),
                       reinterpret_cast<const unsigned*>(&bv));
          }
        };
        if (phase == 0)      { dob(0, 0, z2a); dob(0, 1, z2a); }
        else if (phase == 1) { dob(0, 0, z2a); }
        else if (phase == 2) { dob(1, 0, z2a); dob(1, 1, z2a);
                               dob(2, 0, z1a); dob(2, 1, z1a); }
        else                 { dob(1, 0, z2a); dob(2, 0, z1a); }
      }
      __syncthreads();
    }

    // ---- reduce K-partials: kp1,2,3 write slots; kp0 adds; kp0 writes zbuf ----
    {
      float* slot = nullptr;
      if (kp == 1) slot = reinterpret_cast<float*>(smem + SM_CHUNK) + (mp * 32 + lane) * 64;
      if (kp == 2) slot = reinterpret_cast<float*>(smem + SM_CHUNK + 32768) + (mp * 32 + lane) * 64;
      if (kp == 3) slot = reinterpret_cast<float*>(smem + SM_Z) + (mp * 32 + lane) * 64;
      if (slot) {
#pragma unroll
        for (int i = 0; i < 32; ++i) {
          slot[i]      = reinterpret_cast<float*>(z2a)[i];
          slot[32 + i] = reinterpret_cast<float*>(z1a)[i];
        }
      }
    }
    __syncthreads();
    if (kp == 0) {
      const float* s1 = reinterpret_cast<float*>(smem + SM_CHUNK) + (mp * 32 + lane) * 64;
      const float* s2 = reinterpret_cast<float*>(smem + SM_CHUNK + 32768) + (mp * 32 + lane) * 64;
      const float* s3 = reinterpret_cast<float*>(smem + SM_Z) + (mp * 32 + lane) * 64;
#pragma unroll
      for (int i = 0; i < 32; ++i) {
        reinterpret_cast<float*>(z2a)[i] += s1[i] + s2[i] + s3[i];
        reinterpret_cast<float*>(z1a)[i] += s1[32 + i] + s2[32 + i] + s3[32 + i];
      }
    }
    __syncthreads();
    if (kp == 0) {
      float* zb = reinterpret_cast<float*>(smem + SM_Z);
#pragma unroll
      for (int mt = 0; mt < 4; ++mt)
#pragma unroll
        for (int nt = 0; nt < 2; ++nt)
#pragma unroll
          for (int ci = 0; ci < 4; ++ci) {
            int b  = mp * 64 + mt * 16 + (lane >> 2) + 8 * (ci >> 1);
            int gc = nt * 8 + (lane & 3) * 2 + (ci & 1);
            zb[gc * 257 + b]        = z2a[mt][nt][ci];
            zb[(16 + gc) * 257 + b] = z1a[mt][nt][ci];
          }
    }
    __syncthreads();

    // ---- epilogue layer 2 -> h2(t), opart ----
    const float* zb = reinterpret_cast<const float*>(smem + SM_Z);
    if (tid < 256) {
      int b = tid;
      float hv[4], op = 0.f;
#pragma unroll
      for (int u = 0; u < 4; ++u) {
        float zi = zb[(u) * 257 + b]      + misc[16 + u];
        float zf = zb[(4 + u) * 257 + b]  + misc[16 + 4 + u];
        float zo = zb[(8 + u) * 257 + b]  + misc[16 + 8 + u];
        float zg = zb[(12 + u) * 257 + b] + misc[16 + 12 + u];
        float c = sigf(zf) * c2s[u] + sigf(zi) * tanhf(zg);
        c2s[u] = c;
        hv[u] = sigf(zo) * tanhf(c);
        op = fmaf(hv[u], misc[48 + u], op);
      }
      h_write(g_h2[t & 1], b, cta, hv);
      g_opart[b * NCTA + cta] = op;
    }

    // ---- next input ----
    float xnext = 0.f;
    if (!pred) {
      if (tid < 256) xnext = __ldg(&seq[tid * Tn + (t + 1)]);
    } else {
      grid_barrier(gen);
      if (warp < 2) {
        int ob = 2 * cta + warp;
        float4 v = __ldcg(reinterpret_cast<const float4*>(g_opart + ob * NCTA) + lane);
        float p = v.x + v.y + v.z + v.w;
#pragma unroll
        for (int off = 16; off; off >>= 1) p += __shfl_xor_sync(0xffffffffu, p, off);
        if (lane == 0) g_out[t * 256 + ob] = p;
      }
      grid_barrier(gen);
      if (tid < 256) xnext = __ldcg(&g_out[t * 256 + tid]) + bl0;
    }

    // ---- epilogue layer 1 -> h1(t+1) ----
    if (tid < 256) {
      int b = tid;
      float hv[4];
#pragma unroll
      for (int u = 0; u < 4; ++u) {
        float zi = fmaf(xnext, misc[32 + u],      zb[(16 + u) * 257 + b]      + misc[u]);
        float zf = fmaf(xnext, misc[32 + 4 + u],  zb[(16 + 4 + u) * 257 + b]  + misc[4 + u]);
        float zo = fmaf(xnext, misc[32 + 8 + u],  zb[(16 + 8 + u) * 257 + b]  + misc[8 + u]);
        float zg = fmaf(xnext, misc[32 + 12 + u], zb[(16 + 12 + u) * 257 + b] + misc[12 + u]);
        float c = sigf(zf) * c1s[u] + sigf(zi) * tanhf(zg);
        c1s[u] = c;
        hv[u] = sigf(zo) * tanhf(c);
      }
      h_write(g_h1[(t + 1) & 1], b, cta, hv);
    }
    grid_barrier(gen);
  }

  // out[b][tp] = o + bl
  for (int idx = cta * NTHR + tid; idx < TPn * 256; idx += NCTA * NTHR) {
    int b = idx / TPn, tp = idx - b * TPn;
    out[idx] = __ldcg(&g_out[tp * 256 + b]) + bl0;
  }
}

extern "C" void kernel_launch(void* const* d_in, const int* in_sizes, int n_in,
                              void* d_out, int out_size) {
  (void)in_sizes; (void)n_in; (void)out_size;
  const float* seq = (const float*)d_in[0];
  const float* Wx1 = (const float*)d_in[2];
  const float* bx1 = (const float*)d_in[3];
  const float* Wh1 = (const float*)d_in[4];
  const float* bh1 = (const float*)d_in[5];
  const float* Wx2 = (const float*)d_in[6];
  const float* bx2 = (const float*)d_in[7];
  const float* Wh2 = (const float*)d_in[8];
  const float* bh2 = (const float*)d_in[9];
  const float* Wl  = (const float*)d_in[10];
  const float* bl  = (const float*)d_in[11];

  cudaFuncSetAttribute(sine_rnn_kernel,
                       cudaFuncAttributeMaxDynamicSharedMemorySize, SM_TOTAL);
  sine_rnn_kernel<<<NCTA, NTHR, SM_TOTAL>>>(
      seq, Wx1, bx1, Wh1, bh1, Wx2, bx2, Wh2, bh2, Wl, bl, (float*)d_out);
}

// round 10
// speedup vs baseline: 1.4197x; 1.2034x over previous
#include <cuda_runtime.h>
#include <cuda_fp16.h>

#define NCTA 128
#define NTHR 512
#define Tn   512
#define TPn  544

// SMEM byte map
#define SM_B      0                     // 96KB weight fragments (hi/lo planes)
#define SM_CHUNK  98304                 // 4 x 32KB A-chunk ring (+reduce slots after drain)
#define SM_Z      (SM_CHUNK + 98304)    // zbuf region = ring buf3 (+128B overhang)
#define SM_MISC   (SM_CHUNK + 131200)   // past zbuf end (zbuf = 32*257*4 = 32896 B)
#define SM_TOTAL  (SM_MISC + 256)

#define BOFFU(m,q,p,nt,L) ((((((m)*32+(q))*2+(p))*2+(nt))*32+(L))*2)

__device__ __align__(16) unsigned g_h1[2][131072];  // fp16 planes, A-frag order
__device__ __align__(16) unsigned g_h2[2][131072];
__device__ float    g_opart[256 * NCTA];            // [b][cta]
__device__ float    g_out[TPn * 256];               // [t][b], raw (no bl)
__device__ unsigned g_flags[NCTA];

__device__ __forceinline__ float sigf(float x) { return 1.f / (1.f + __expf(-x)); }

__device__ __forceinline__ void mma16816(float* c, const unsigned* a, const unsigned* b) {
  asm volatile(
      "mma.sync.aligned.m16n8k16.row.col.f32.f16.f16.f32 "
      "{%0,%1,%2,%3},{%4,%5,%6,%7},{%8,%9},{%0,%1,%2,%3};\n"
      : "+f"(c[0]), "+f"(c[1]), "+f"(c[2]), "+f"(c[3])
      : "r"(a[0]), "r"(a[1]), "r"(a[2]), "r"(a[3]), "r"(b[0]), "r"(b[1]));
}

__device__ __forceinline__ void cp_async16(unsigned sdst, const void* gsrc) {
  asm volatile("cp.async.cg.shared.global [%0], [%1], 16;\n" :: "r"(sdst), "l"(gsrc));
}
__device__ __forceinline__ void cp_commit() { asm volatile("cp.async.commit_group;\n"); }
__device__ __forceinline__ void cp_wait3()  { asm volatile("cp.async.wait_group 3;\n"); }
__device__ __forceinline__ void cp_wait2()  { asm volatile("cp.async.wait_group 2;\n"); }
__device__ __forceinline__ void cp_wait1()  { asm volatile("cp.async.wait_group 1;\n"); }
__device__ __forceinline__ void cp_wait0()  { asm volatile("cp.async.wait_group 0;\n"); }

__device__ __forceinline__ void grid_barrier(unsigned& gen) {
  __threadfence();
  __syncthreads();
  ++gen;
  if (threadIdx.x == 0)
    asm volatile("st.release.gpu.u32 [%0], %1;" :: "l"(&g_flags[blockIdx.x]), "r"(gen));
  if (threadIdx.x < NCTA) {
    unsigned v;
    do {
      asm volatile("ld.acquire.gpu.u32 %0, [%1];" : "=r"(v) : "l"(&g_flags[threadIdx.x]));
    } while ((int)(v - gen) < 0);
  }
  __syncthreads();
}

// write h[b][u0..u0+3] as hi/lo fp16 planes in A-fragment order
__device__ __forceinline__ void h_write(unsigned* gb, int b, int cta, const float* hv) {
  int q = cta >> 2, kcb = (cta & 3) * 4, mtg = b >> 4;
  __half hh[4], hl[4];
#pragma unroll
  for (int u = 0; u < 4; ++u) {
    hh[u] = __float2half_rn(hv[u]);
    hl[u] = __float2half_rn(hv[u] - __half2float(hh[u]));
  }
#pragma unroll
  for (int j = 0; j < 2; ++j) {
    int kc0 = kcb + 2 * j;
    int L   = ((b & 7) << 2) | ((kc0 & 7) >> 1);
    int rg  = ((b >> 3) & 1) | ((kc0 >> 3) << 1);
    __half2 vh = __halves2half2(hh[2 * j], hh[2 * j + 1]);
    __half2 vl = __halves2half2(hl[2 * j], hl[2 * j + 1]);
    gb[((q * 2 + 0) * 16 + mtg) * 128 + L * 4 + rg] = *reinterpret_cast<unsigned*>(&vh);
    gb[((q * 2 + 1) * 16 + mtg) * 128 + L * 4 + rg] = *reinterpret_cast<unsigned*>(&vl);
  }
}

__global__ void __launch_bounds__(NTHR, 1) sine_rnn_kernel(
    const float* __restrict__ seq,
    const float* __restrict__ Wx1, const float* __restrict__ bx1,
    const float* __restrict__ Wh1, const float* __restrict__ bh1,
    const float* __restrict__ Wx2, const float* __restrict__ bx2,
    const float* __restrict__ Wh2, const float* __restrict__ bh2,
    const float* __restrict__ Wl,  const float* __restrict__ bl,
    float* __restrict__ out)
{
  extern __shared__ char smem[];
  const unsigned sb = (unsigned)__cvta_generic_to_shared(smem);
  const int tid  = threadIdx.x;
  const int lane = tid & 31;
  const int warp = tid >> 5;
  const int kp   = warp & 3;   // K-part (128 k each)
  const int mp   = warp >> 2;  // M-part (64 batches each)
  const int cta  = blockIdx.x;
  const int u0   = cta * 4;
  const float bl0 = __ldg(&bl[0]);

  float* misc = reinterpret_cast<float*>(smem + SM_MISC);
  // ---- init: weight fragments (hi/lo) + misc ----
  for (int idx = tid; idx < 3 * 512 * 16; idx += NTHR) {
    int m = idx >> 13, r = idx & 8191, k = r >> 4, gc = r & 15;
    int col = u0 + (gc & 3) + ((gc >> 2) << 9);
    const float* Wm = (m == 0) ? Wh2 : ((m == 1) ? Wx2 : Wh1);
    float v = Wm[k * 2048 + col];
    __half hi = __float2half_rn(v);
    __half lo = __float2half_rn(v - __half2float(hi));
    int q = k >> 4, kc = k & 15, nt = gc >> 3, n = gc & 7;
    int L = (n << 2) | ((kc & 7) >> 1), rg = kc >> 3, hf = kc & 1;
    __half* hp = reinterpret_cast<__half*>(smem + SM_B);
    hp[(BOFFU(m, q, 0, nt, L) + rg) * 2 + hf] = hi;
    hp[(BOFFU(m, q, 1, nt, L) + rg) * 2 + hf] = lo;
  }
  if (tid < 16) {
    int gc = tid;
    int col = u0 + (gc & 3) + ((gc >> 2) << 9);
    misc[gc]      = bx1[col] + bh1[col];
    misc[16 + gc] = bx2[col] + bh2[col];
    misc[32 + gc] = Wx1[col];
  }
  if (tid < 4) misc[48 + tid] = Wl[u0 + tid];
  __syncthreads();

  float c1s[4] = {0, 0, 0, 0}, c2s[4] = {0, 0, 0, 0};

  // h1(0) from x(0); zero slice of g_h2[1]
  if (tid < 256) {
    int b = tid;
    float x0 = __ldg(&seq[b * Tn]);
    float hv[4];
#pragma unroll
    for (int u = 0; u < 4; ++u) {
      float zi = fmaf(x0, misc[32 + u],      misc[u]);
      float zo = fmaf(x0, misc[32 + 8 + u],  misc[8 + u]);
      float zg = fmaf(x0, misc[32 + 12 + u], misc[12 + u]);
      float c = sigf(zi) * tanhf(zg);
      c1s[u] = c;
      hv[u] = sigf(zo) * tanhf(c);
    }
    h_write(g_h1[0], b, cta, hv);
  }
  for (int i = tid; i < 1024; i += NTHR) g_h2[1][cta * 1024 + i] = 0u;

  unsigned gen;
  asm volatile("ld.acquire.gpu.u32 %0, [%1];" : "=r"(gen) : "l"(&g_flags[cta]));
  grid_barrier(gen);

  for (int t = 0; t < TPn; ++t) {
    const bool pred = (t >= Tn - 1);

    const unsigned* src_h2 = g_h2[(t ^ 1) & 1];
    const unsigned* src_h1 = g_h1[t & 1];

    // ---- warp-private staging: warp w stages ONLY the 2KB it will consume ----
    auto stage_w = [&](int cc) {
      int phase = cc >> 3, rr = cc & 7;
      int q = kp * 8 + rr;
      const unsigned* gsrc = ((phase < 2) ? src_h2 : src_h1) +
                             (q * 2 + (phase & 1)) * 2048 + mp * 512;
      unsigned dst = sb + SM_CHUNK + (unsigned)(cc & 3) * 32768u +
                     (unsigned)warp * 2048u;
#pragma unroll
      for (int j = 0; j < 4; ++j)
        cp_async16(dst + (unsigned)(j * 32 + lane) * 16u, gsrc + (j * 32 + lane) * 4);
      cp_commit();
    };

    // main-phase o(t-1): owner reduces partials
    if (t >= 1 && t <= Tn - 1 && warp < 2) {
      int ob = 2 * cta + warp;
      float4 v = __ldcg(reinterpret_cast<const float4*>(g_opart + ob * NCTA) + lane);
      float p = v.x + v.y + v.z + v.w;
#pragma unroll
      for (int off = 16; off; off >>= 1) p += __shfl_xor_sync(0xffffffffu, p, off);
      if (lane == 0) g_out[(t - 1) * 256 + ob] = p;
    }

    float z2a[4][2][4], z1a[4][2][4];
#pragma unroll
    for (int i = 0; i < 32; ++i) {
      reinterpret_cast<float*>(z2a)[i] = 0.f;
      reinterpret_cast<float*>(z1a)[i] = 0.f;
    }

    stage_w(0); stage_w(1); stage_w(2);

    // 32 chunks, ZERO block barriers: per-warp in-order pipeline, depth 4
    for (int cc = 0; cc < 32; ++cc) {
      if (cc < 29)      { stage_w(cc + 3); cp_wait3(); }
      else if (cc == 29) cp_wait2();
      else if (cc == 30) cp_wait1();
      else               cp_wait0();

      {
        int phase = cc >> 3, rr = cc & 7;
        int q = kp * 8 + rr;
        const char* ab = smem + SM_CHUNK + (cc & 3) * 32768 +
                         warp * 2048 + lane * 16;
        uint4 a[4];
#pragma unroll
        for (int mt = 0; mt < 4; ++mt)
          a[mt] = *reinterpret_cast<const uint4*>(ab + mt * 512);
        auto dob = [&](int m, int p, float (*acc)[2][4]) {
#pragma unroll
          for (int nt = 0; nt < 2; ++nt) {
            uint2 bv = *reinterpret_cast<const uint2*>(
                smem + SM_B + BOFFU(m, q, p, nt, lane) * 4);
#pragma unroll
            for (int mt = 0; mt < 4; ++mt)
              mma16816(acc[mt][nt], reinterpret_cast<const unsigned*>(&a[mt]),
                       reinterpret_cast<const unsigned*>(&bv));
          }
        };
        if (phase == 0)      { dob(0, 0, z2a); dob(0, 1, z2a); }
        else if (phase == 1) { dob(0, 0, z2a); }
        else if (phase == 2) { dob(1, 0, z2a); dob(1, 1, z2a);
                               dob(2, 0, z1a); dob(2, 1, z1a); }
        else                 { dob(1, 0, z2a); dob(2, 0, z1a); }
      }
    }
    __syncthreads();  // all compute done; ring buffers now reusable as slots

    // ---- reduce K-partials: kp1->buf0, kp2->buf1, kp3->buf2 ----
    {
      float* slot = nullptr;
      if (kp == 1) slot = reinterpret_cast<float*>(smem + SM_CHUNK) + (mp * 32 + lane) * 64;
      if (kp == 2) slot = reinterpret_cast<float*>(smem + SM_CHUNK + 32768) + (mp * 32 + lane) * 64;
      if (kp == 3) slot = reinterpret_cast<float*>(smem + SM_CHUNK + 65536) + (mp * 32 + lane) * 64;
      if (slot) {
#pragma unroll
        for (int i = 0; i < 32; ++i) {
          slot[i]      = reinterpret_cast<float*>(z2a)[i];
          slot[32 + i] = reinterpret_cast<float*>(z1a)[i];
        }
      }
    }
    __syncthreads();
    if (kp == 0) {
      const float* s1 = reinterpret_cast<float*>(smem + SM_CHUNK) + (mp * 32 + lane) * 64;
      const float* s2 = reinterpret_cast<float*>(smem + SM_CHUNK + 32768) + (mp * 32 + lane) * 64;
      const float* s3 = reinterpret_cast<float*>(smem + SM_CHUNK + 65536) + (mp * 32 + lane) * 64;
#pragma unroll
      for (int i = 0; i < 32; ++i) {
        reinterpret_cast<float*>(z2a)[i] += s1[i] + s2[i] + s3[i];
        reinterpret_cast<float*>(z1a)[i] += s1[32 + i] + s2[32 + i] + s3[32 + i];
      }
      float* zb = reinterpret_cast<float*>(smem + SM_Z);
#pragma unroll
      for (int mt = 0; mt < 4; ++mt)
#pragma unroll
        for (int nt = 0; nt < 2; ++nt)
#pragma unroll
          for (int ci = 0; ci < 4; ++ci) {
            int b  = mp * 64 + mt * 16 + (lane >> 2) + 8 * (ci >> 1);
            int gc = nt * 8 + (lane & 3) * 2 + (ci & 1);
            zb[gc * 257 + b]        = z2a[mt][nt][ci];
            zb[(16 + gc) * 257 + b] = z1a[mt][nt][ci];
          }
    }
    __syncthreads();

    // ---- epilogue layer 2 -> h2(t), opart ----
    const float* zb = reinterpret_cast<const float*>(smem + SM_Z);
    if (tid < 256) {
      int b = tid;
      float hv[4], op = 0.f;
#pragma unroll
      for (int u = 0; u < 4; ++u) {
        float zi = zb[(u) * 257 + b]      + misc[16 + u];
        float zf = zb[(4 + u) * 257 + b]  + misc[16 + 4 + u];
        float zo = zb[(8 + u) * 257 + b]  + misc[16 + 8 + u];
        float zg = zb[(12 + u) * 257 + b] + misc[16 + 12 + u];
        float c = sigf(zf) * c2s[u] + sigf(zi) * tanhf(zg);
        c2s[u] = c;
        hv[u] = sigf(zo) * tanhf(c);
        op = fmaf(hv[u], misc[48 + u], op);
      }
      h_write(g_h2[t & 1], b, cta, hv);
      g_opart[b * NCTA + cta] = op;
    }

    // ---- next input ----
    float xnext = 0.f;
    if (!pred) {
      if (tid < 256) xnext = __ldg(&seq[tid * Tn + (t + 1)]);
    } else {
      grid_barrier(gen);
      if (warp < 2) {
        int ob = 2 * cta + warp;
        float4 v = __ldcg(reinterpret_cast<const float4*>(g_opart + ob * NCTA) + lane);
        float p = v.x + v.y + v.z + v.w;
#pragma unroll
        for (int off = 16; off; off >>= 1) p += __shfl_xor_sync(0xffffffffu, p, off);
        if (lane == 0) g_out[t * 256 + ob] = p;
      }
      grid_barrier(gen);
      if (tid < 256) xnext = __ldcg(&g_out[t * 256 + tid]) + bl0;
    }

    // ---- epilogue layer 1 -> h1(t+1) ----
    if (tid < 256) {
      int b = tid;
      float hv[4];
#pragma unroll
      for (int u = 0; u < 4; ++u) {
        float zi = fmaf(xnext, misc[32 + u],      zb[(16 + u) * 257 + b]      + misc[u]);
        float zf = fmaf(xnext, misc[32 + 4 + u],  zb[(16 + 4 + u) * 257 + b]  + misc[4 + u]);
        float zo = fmaf(xnext, misc[32 + 8 + u],  zb[(16 + 8 + u) * 257 + b]  + misc[8 + u]);
        float zg = fmaf(xnext, misc[32 + 12 + u], zb[(16 + 12 + u) * 257 + b] + misc[12 + u]);
        float c = sigf(zf) * c1s[u] + sigf(zi) * tanhf(zg);
        c1s[u] = c;
        hv[u] = sigf(zo) * tanhf(c);
      }
      h_write(g_h1[(t + 1) & 1], b, cta, hv);
    }
    grid_barrier(gen);
  }

  // out[b][tp] = o + bl
  for (int idx = cta * NTHR + tid; idx < TPn * 256; idx += NCTA * NTHR) {
    int b = idx / TPn, tp = idx - b * TPn;
    out[idx] = __ldcg(&g_out[tp * 256 + b]) + bl0;
  }
}

extern "C" void kernel_launch(void* const* d_in, const int* in_sizes, int n_in,
                              void* d_out, int out_size) {
  (void)in_sizes; (void)n_in; (void)out_size;
  const float* seq = (const float*)d_in[0];
  const float* Wx1 = (const float*)d_in[2];
  const float* bx1 = (const float*)d_in[3];
  const float* Wh1 = (const float*)d_in[4];
  const float* bh1 = (const float*)d_in[5];
  const float* Wx2 = (const float*)d_in[6];
  const float* bx2 = (const float*)d_in[7];
  const float* Wh2 = (const float*)d_in[8];
  const float* bh2 = (const float*)d_in[9];
  const float* Wl  = (const float*)d_in[10];
  const float* bl  = (const float*)d_in[11];

  cudaFuncSetAttribute(sine_rnn_kernel,
                       cudaFuncAttributeMaxDynamicSharedMemorySize, SM_TOTAL);
  sine_rnn_kernel<<<NCTA, NTHR, SM_TOTAL>>>(
      seq, Wx1, bx1, Wh1, bh1, Wx2, bx2, Wh2, bh2, Wl, bl, (float*)d_out);
}